// round 14
// baseline (speedup 1.0000x reference)
#include <cuda_runtime.h>
#include <cuda_bf16.h>
#include <cstdint>

#define NPIX   262144
#define CD     256
#define HW     16384
#define TILE_P 32
#define NTILES (NPIX / TILE_P)      // 8192 tiles of 32 px
#define GRID   148
#define NTHR   512                  // 2 domains x 256
#define NDOM_G (GRID * 2)           // 296 global domains
// queue prescale: (1/T) * log2(e)  -> epilogue uses ex2 directly
#define QSCALE 20.60992915555662f

// smem layout (bytes)
#define B_STRIDE 528                  // 132 words = 4 mod 32 banks: conflict-free ldsm
#define A_STRIDE 80                   // 20 words: conflict-free ldsm
#define A_BUF    (256 * A_STRIDE)     // 20480 per buffer
#define OFF_B    0                    // 256*528 = 135168
#define OFF_A    135168               // 4 buffers (dom,parity) -> +81920
#define OFF_LAB  (OFF_A + 4 * A_BUF)  // 217088 : 4 x 1024 (32 px * 32 bytes)
#define SMEM_SZ  (OFF_LAB + 4 * 1024 + 64)   // 221248

#define FIN_BLKS 512

__device__ float g_en[NTILES * 256];     // [tile][wn 0..7][row 0..31]  8MB
__device__ float g_ep[NTILES * 256];     // 8MB
__device__ float g_partial[FIN_BLKS];
__device__ int   g_pcnt[FIN_BLKS];

__device__ __forceinline__ uint32_t smem_u32(const void* p) {
    uint32_t a;
    asm("{ .reg .u64 t; cvta.to.shared.u64 t, %1; cvt.u32.u64 %0, t; }" : "=r"(a) : "l"(p));
    return a;
}
__device__ __forceinline__ void ldsm_x4(uint32_t* r, uint32_t addr) {
    asm volatile("ldmatrix.sync.aligned.m8n8.x4.shared.b16 {%0,%1,%2,%3}, [%4];"
                 : "=r"(r[0]), "=r"(r[1]), "=r"(r[2]), "=r"(r[3]) : "r"(addr));
}
__device__ __forceinline__ void ldsm_x4_t(uint32_t* r, uint32_t addr) {
    asm volatile("ldmatrix.sync.aligned.m8n8.x4.trans.shared.b16 {%0,%1,%2,%3}, [%4];"
                 : "=r"(r[0]), "=r"(r[1]), "=r"(r[2]), "=r"(r[3]) : "r"(addr));
}
__device__ __forceinline__ void mma_bf16(float* d, const uint32_t* a,
                                         uint32_t b0, uint32_t b1) {
    asm volatile(
        "mma.sync.aligned.m16n8k16.row.col.f32.bf16.bf16.f32 "
        "{%0,%1,%2,%3}, {%4,%5,%6,%7}, {%8,%9}, {%0,%1,%2,%3};"
        : "+f"(d[0]), "+f"(d[1]), "+f"(d[2]), "+f"(d[3])
        : "r"(a[0]), "r"(a[1]), "r"(a[2]), "r"(a[3]), "r"(b0), "r"(b1));
}
__device__ __forceinline__ float ex2(float x) {
    float r;
    asm("ex2.approx.f32 %0, %1;" : "=f"(r) : "f"(x));
    return r;
}
// labels are {0,1} int32 (randint 0,2): pack via arithmetic (no ISETP chain)
__device__ __forceinline__ unsigned mask8(const int4& v0, const int4& v1) {
    unsigned m;
    m  = ((unsigned)v0.x & 1u);
    m += ((unsigned)v0.y & 1u) << 1;
    m += ((unsigned)v0.z & 1u) << 2;
    m += ((unsigned)v0.w & 1u) << 3;
    m += ((unsigned)v1.x & 1u) << 4;
    m += ((unsigned)v1.y & 1u) << 5;
    m += ((unsigned)v1.z & 1u) << 6;
    m += ((unsigned)v1.w & 1u) << 7;
    return m;
}

// ===================== persistent fused main kernel =====================
// 148 CTAs x 512 thr = 2 independent domains of 256 thr (8 warps, warp tile
// 32x32, warp grid 1x8 over a 32px x 256cls tile). Queue shared read-only.
// Epilogue: s = sum(exp(l xor y·sign)) = en+ep; ep = sum(fy*e); en = s - ep.
__global__ void __launch_bounds__(NTHR, 1)
pcl_main(const float* __restrict__ feats, const float* __restrict__ queue,
         const int* __restrict__ labels)
{
    extern __shared__ char smem[];
    const uint32_t sb = smem_u32(smem);
    const int tid = threadIdx.x, lane = tid & 31;
    const int dom = tid >> 8;            // 0..1
    const int dtid = tid & 255;          // thread within domain
    const int wn = dtid >> 5;            // 0..7 : class column of this warp
    const int gd = blockIdx.x * 2 + dom; // global domain id 0..295

    // ---- stage B once (whole block): queue fp32 -> bf16, prescaled ----
    for (int i = tid; i < 256 * 128; i += NTHR) {
        int n = i >> 7, k2 = i & 127;
        float2 v = *(const float2*)(queue + n * 256 + k2 * 2);
        *(__nv_bfloat162*)(smem + OFF_B + n * B_STRIDE + k2 * 4) =
            __floats2bfloat162_rn(v.x * QSCALE, v.y * QSCALE);
    }
    // ---- stage first tile (per domain, buffer parity 0) ----
    {
        const int n0 = gd * TILE_P;
        const float* fp = feats + (size_t)(n0 / HW) * CD * HW + (n0 % HW);
        char* a0 = smem + OFF_A + (dom * 2) * A_BUF;
        for (int i = dtid; i < 256 * 16; i += 256) {
            int row = i >> 4, p2 = i & 15;
            float2 v = *(const float2*)(fp + (size_t)row * HW + p2 * 2);
            *(__nv_bfloat162*)(a0 + row * A_STRIDE + p2 * 4) =
                __floats2bfloat162_rn(v.x, v.y);
        }
        const int* lp = labels + (size_t)n0 * 256;
        unsigned char* lm0 = (unsigned char*)(smem + OFF_LAB + (dom * 2) * 1024);
        for (int s = dtid; s < 1024; s += 256) {
            int px = s >> 5, sub = s & 31;
            const int4* l4 = (const int4*)(lp + px * 256 + sub * 8);
            lm0[px * 32 + sub] = (unsigned char)mask8(l4[0], l4[1]);
        }
    }
    __syncthreads();   // B + both domains' first tiles visible

    // ldsm lane decomposition
    const int r8   = lane & 7;
    const int sel8 = (lane >> 3) & 1;
    const int selk = (lane >> 4) & 1;
    const uint32_t b_base = sb + OFF_B
        + (uint32_t)(wn * 32 + sel8 * 8 + r8) * B_STRIDE + (uint32_t)selk * 16;
    const uint32_t b_base2 = b_base + 16 * B_STRIDE;
    const uint32_t a_lane_off =
        (uint32_t)(selk * 8 + r8) * A_STRIDE + (uint32_t)sel8 * 16;

    int p = 0;  // buffer parity (per domain)
#pragma unroll 1
    for (int cur = gd; cur < NTILES; cur += NDOM_G, p ^= 1) {
        const int nxt = cur + NDOM_G;
        const bool pf = nxt < NTILES;
        const uint32_t a_base = sb + OFF_A + (uint32_t)(dom * 2 + p) * A_BUF + a_lane_off;
        char* anxt = smem + OFF_A + (dom * 2 + (p ^ 1)) * A_BUF;
        unsigned char* lmnxt = (unsigned char*)(smem + OFF_LAB + (dom * 2 + (p ^ 1)) * 1024);
        const float* fnx = nullptr; const int* lnx = nullptr;
        if (pf) {
            const int nn0 = nxt * TILE_P;
            fnx = feats + (size_t)(nn0 / HW) * CD * HW + (nn0 % HW);
            lnx = labels + (size_t)nn0 * 256;
        }

        float acc[2][4][4];
#pragma unroll
        for (int mb = 0; mb < 2; mb++)
#pragma unroll
            for (int nb = 0; nb < 4; nb++)
#pragma unroll
                for (int e = 0; e < 4; e++) acc[mb][nb][e] = 0.0f;

#pragma unroll
        for (int g = 0; g < 4; g++) {
            // prefetch tile nxt: A rows [g*64, g*64+64), label slots [g*256, +256)
            float4 pa0, pa1; int4 pl0, pl1;
            const int rowp = g * 64 + (dtid >> 2);
            const int q4 = dtid & 3;
            const int slot = g * 256 + dtid, pxl = slot >> 5, sub = slot & 31;
            if (pf) {
                const float4* asrc = (const float4*)(fnx + (size_t)rowp * HW);
                pa0 = asrc[q4]; pa1 = asrc[q4 + 4];
                const int4* lsrc = (const int4*)(lnx + pxl * 256 + sub * 8);
                pl0 = lsrc[0]; pl1 = lsrc[1];
            }
            // 4 ksteps of mma on tile cur (k-group g)
#pragma unroll
            for (int kk = 0; kk < 4; kk++) {
                const int ks = g * 4 + kk;
                uint32_t a[2][4], bq[2][4];
                ldsm_x4_t(a[0], a_base + (uint32_t)ks * 16 * A_STRIDE);
                ldsm_x4_t(a[1], a_base + (uint32_t)ks * 16 * A_STRIDE + 32);
                ldsm_x4(bq[0], b_base + (uint32_t)ks * 32);
                ldsm_x4(bq[1], b_base2 + (uint32_t)ks * 32);
#pragma unroll
                for (int mb = 0; mb < 2; mb++)
#pragma unroll
                    for (int nbp = 0; nbp < 2; nbp++) {
                        mma_bf16(acc[mb][2 * nbp],     a[mb], bq[nbp][0], bq[nbp][2]);
                        mma_bf16(acc[mb][2 * nbp + 1], a[mb], bq[nbp][1], bq[nbp][3]);
                    }
            }
            // drain prefetch into nxt buffers
            if (pf) {
                __nv_bfloat162 lo0 = __floats2bfloat162_rn(pa0.x, pa0.y);
                __nv_bfloat162 hi0 = __floats2bfloat162_rn(pa0.z, pa0.w);
                uint2 v0 = { *(uint32_t*)&lo0, *(uint32_t*)&hi0 };
                *(uint2*)(anxt + rowp * A_STRIDE + q4 * 8) = v0;
                __nv_bfloat162 lo1 = __floats2bfloat162_rn(pa1.x, pa1.y);
                __nv_bfloat162 hi1 = __floats2bfloat162_rn(pa1.z, pa1.w);
                uint2 v1 = { *(uint32_t*)&lo1, *(uint32_t*)&hi1 };
                *(uint2*)(anxt + rowp * A_STRIDE + (q4 + 4) * 8) = v1;
                lmnxt[pxl * 32 + sub] = (unsigned char)mask8(pl0, pl1);
            }
        }

        // ---- epilogue tile cur: s/ep form, no selects, no barrier ----
        const unsigned* labm = (const unsigned*)(smem + OFF_LAB + (dom * 2 + p) * 1024);
#pragma unroll
        for (int mb = 0; mb < 2; mb++) {
#pragma unroll
            for (int half = 0; half < 2; half++) {
                const int row = mb * 16 + (lane >> 2) + half * 8;   // 0..31
                const unsigned mw = labm[row * 8 + wn];
                float s = 0.0f, ep = 0.0f;
#pragma unroll
                for (int nb = 0; nb < 4; nb++) {
                    const int sh = nb * 8 + (lane & 3) * 2;
                    const unsigned bit0 = (mw >> sh) & 1u;
                    const unsigned bit1 = (mw >> (sh + 1)) & 1u;
                    float l0 = acc[mb][nb][half * 2];
                    float l1 = acc[mb][nb][half * 2 + 1];
                    // e = ex2( l xor (y ? signbit : 0) )
                    float e0 = ex2(__uint_as_float(__float_as_uint(l0) ^ (bit0 << 31)));
                    float e1 = ex2(__uint_as_float(__float_as_uint(l1) ^ (bit1 << 31)));
                    s += e0;
                    s += e1;
                    ep = fmaf(e0, __uint_as_float(bit0 * 0x3F800000u), ep);
                    ep = fmaf(e1, __uint_as_float(bit1 * 0x3F800000u), ep);
                }
                s  += __shfl_xor_sync(0xffffffffu, s, 1);
                s  += __shfl_xor_sync(0xffffffffu, s, 2);
                ep += __shfl_xor_sync(0xffffffffu, ep, 1);
                ep += __shfl_xor_sync(0xffffffffu, ep, 2);
                if ((lane & 3) == 0) {   // deterministic per-(tile,wn,row) slots
                    const int slot = cur * 256 + wn * 32 + row;
                    g_en[slot] = s - ep;   // en = s - ep
                    g_ep[slot] = ep;
                }
            }
        }
        // domain-private barrier: flip this domain's double buffers only
        asm volatile("bar.sync %0, 256;" :: "r"(dom + 1) : "memory");
    }
}

// ===================== finalize 1: combine wn partials, per-block reduce =====
__global__ void __launch_bounds__(512) pcl_fin1()
{
    __shared__ float ss[16];
    __shared__ int   sc[16];
    const int n = blockIdx.x * 512 + threadIdx.x;   // pixel id
    const int tile = n >> 5, row = n & 31;
    const int base = tile * 256 + row;
    float en = 0.0f, ep = 0.0f;
#pragma unroll
    for (int w = 0; w < 8; w++) {
        en += g_en[base + w * 32];
        ep += g_ep[base + w * 32];
    }
    float loss = __logf(en * ep + 1.0f);
    int   cnt  = (loss != 0.0f) ? 1 : 0;
#pragma unroll
    for (int off = 16; off > 0; off >>= 1) {
        loss += __shfl_xor_sync(0xffffffffu, loss, off);
        cnt  += __shfl_xor_sync(0xffffffffu, cnt,  off);
    }
    const int lane = threadIdx.x & 31, wid = threadIdx.x >> 5;
    if (lane == 0) { ss[wid] = loss; sc[wid] = cnt; }
    __syncthreads();
    if (threadIdx.x == 0) {
        float s = 0.0f; int c = 0;
#pragma unroll
        for (int w = 0; w < 16; w++) { s += ss[w]; c += sc[w]; }
        g_partial[blockIdx.x] = s;
        g_pcnt[blockIdx.x]    = c;
    }
}

// ===================== finalize 2: scalar =====================
__global__ void __launch_bounds__(512) pcl_fin2(float* __restrict__ out)
{
    __shared__ float ss[16];
    __shared__ int   sc[16];
    float s = g_partial[threadIdx.x];
    int   c = g_pcnt[threadIdx.x];
#pragma unroll
    for (int off = 16; off > 0; off >>= 1) {
        s += __shfl_xor_sync(0xffffffffu, s, off);
        c += __shfl_xor_sync(0xffffffffu, c, off);
    }
    const int lane = threadIdx.x & 31, wid = threadIdx.x >> 5;
    if (lane == 0) { ss[wid] = s; sc[wid] = c; }
    __syncthreads();
    if (threadIdx.x == 0) {
        float t = 0.0f; int c2 = 0;
#pragma unroll
        for (int w = 0; w < 16; w++) { t += ss[w]; c2 += sc[w]; }
        out[0] = (c2 == 0) ? 0.0f : t / (float)(c2 < 1 ? 1 : c2);
    }
}

extern "C" void kernel_launch(void* const* d_in, const int* in_sizes, int n_in,
                              void* d_out, int out_size)
{
    const float* feats  = (const float*)d_in[0];
    const float* queue  = (const float*)d_in[1];
    const int*   labels = (const int*)d_in[2];
    float* out = (float*)d_out;

    static bool attr_set = false;
    if (!attr_set) {
        cudaFuncSetAttribute(pcl_main,
                             cudaFuncAttributeMaxDynamicSharedMemorySize, SMEM_SZ);
        attr_set = true;
    }

    pcl_main<<<GRID, NTHR, SMEM_SZ>>>(feats, queue, labels);
    pcl_fin1<<<FIN_BLKS, 512>>>();
    pcl_fin2<<<1, 512>>>(out);
}

// round 15
// speedup vs baseline: 1.0245x; 1.0245x over previous
#include <cuda_runtime.h>
#include <cuda_bf16.h>
#include <cstdint>

#define NPIX   262144
#define CD     256
#define HW     16384
#define TILE_P 32
#define NTILES (NPIX / TILE_P)      // 8192 tiles of 32 px
#define GRID   148
#define NTHR   512                  // 2 domains x 256
#define NDOM_G (GRID * 2)           // 296 global domains
// queue prescale: (1/T) * log2(e)  -> epilogue uses ex2 directly
#define QSCALE 20.60992915555662f

// smem layout (bytes)
#define B_STRIDE 528                  // 132 words = 4 mod 32 banks: conflict-free ldsm
#define A_STRIDE 80                   // 20 words: conflict-free ldsm
#define A_BUF    (256 * A_STRIDE)     // 20480 per buffer
#define OFF_B    0                    // 256*528 = 135168
#define OFF_A    135168               // 4 buffers (dom,parity) -> +81920
#define OFF_LAB  (OFF_A + 4 * A_BUF)  // 217088 : 4 x 1024 (32 px * 32 bytes)
#define OFF_RED  (OFF_LAB + 4 * 1024) // 221184 : 4 x 2048 (32 rows x 8 wn x float2)
#define SMEM_SZ  (OFF_RED + 4 * 2048) // 229376  (< 227KB = 232448 opt-in cap)

__device__ float g_partial[NDOM_G];
__device__ int   g_pcnt[NDOM_G];

__device__ __forceinline__ uint32_t smem_u32(const void* p) {
    uint32_t a;
    asm("{ .reg .u64 t; cvta.to.shared.u64 t, %1; cvt.u32.u64 %0, t; }" : "=r"(a) : "l"(p));
    return a;
}
__device__ __forceinline__ void ldsm_x4(uint32_t* r, uint32_t addr) {
    asm volatile("ldmatrix.sync.aligned.m8n8.x4.shared.b16 {%0,%1,%2,%3}, [%4];"
                 : "=r"(r[0]), "=r"(r[1]), "=r"(r[2]), "=r"(r[3]) : "r"(addr));
}
__device__ __forceinline__ void ldsm_x4_t(uint32_t* r, uint32_t addr) {
    asm volatile("ldmatrix.sync.aligned.m8n8.x4.trans.shared.b16 {%0,%1,%2,%3}, [%4];"
                 : "=r"(r[0]), "=r"(r[1]), "=r"(r[2]), "=r"(r[3]) : "r"(addr));
}
__device__ __forceinline__ void mma_bf16(float* d, const uint32_t* a,
                                         uint32_t b0, uint32_t b1) {
    asm volatile(
        "mma.sync.aligned.m16n8k16.row.col.f32.bf16.bf16.f32 "
        "{%0,%1,%2,%3}, {%4,%5,%6,%7}, {%8,%9}, {%0,%1,%2,%3};"
        : "+f"(d[0]), "+f"(d[1]), "+f"(d[2]), "+f"(d[3])
        : "r"(a[0]), "r"(a[1]), "r"(a[2]), "r"(a[3]), "r"(b0), "r"(b1));
}
__device__ __forceinline__ float ex2(float x) {
    float r;
    asm("ex2.approx.f32 %0, %1;" : "=f"(r) : "f"(x));
    return r;
}
// labels are {0,1} int32 (randint 0,2): pack via arithmetic (no ISETP chain)
__device__ __forceinline__ unsigned mask8(const int4& v0, const int4& v1) {
    unsigned m;
    m  = ((unsigned)v0.x & 1u);
    m += ((unsigned)v0.y & 1u) << 1;
    m += ((unsigned)v0.z & 1u) << 2;
    m += ((unsigned)v0.w & 1u) << 3;
    m += ((unsigned)v1.x & 1u) << 4;
    m += ((unsigned)v1.y & 1u) << 5;
    m += ((unsigned)v1.z & 1u) << 6;
    m += ((unsigned)v1.w & 1u) << 7;
    return m;
}

// ===================== persistent fused main kernel =====================
// 148 CTAs x 512 thr = 2 independent domains of 256 thr (8 warps, warp tile
// 32x32). Per tile: epilogue stages (s,ep) per (row,wn) into smem; after the
// domain barrier, warp 0 of the domain folds the 8 wn partials per pixel,
// computes loss, and accumulates a deterministic running sum per domain.
__global__ void __launch_bounds__(NTHR, 1)
pcl_main(const float* __restrict__ feats, const float* __restrict__ queue,
         const int* __restrict__ labels)
{
    extern __shared__ char smem[];
    const uint32_t sb = smem_u32(smem);
    const int tid = threadIdx.x, lane = tid & 31;
    const int dom = tid >> 8;            // 0..1
    const int dtid = tid & 255;          // thread within domain
    const int wn = dtid >> 5;            // 0..7 : class column of this warp
    const int gd = blockIdx.x * 2 + dom; // global domain id 0..295

    // ---- stage B once (whole block): queue fp32 -> bf16, prescaled ----
    for (int i = tid; i < 256 * 128; i += NTHR) {
        int n = i >> 7, k2 = i & 127;
        float2 v = *(const float2*)(queue + n * 256 + k2 * 2);
        *(__nv_bfloat162*)(smem + OFF_B + n * B_STRIDE + k2 * 4) =
            __floats2bfloat162_rn(v.x * QSCALE, v.y * QSCALE);
    }
    // ---- stage first tile (per domain, buffer parity 0) ----
    {
        const int n0 = gd * TILE_P;
        const float* fp = feats + (size_t)(n0 / HW) * CD * HW + (n0 % HW);
        char* a0 = smem + OFF_A + (dom * 2) * A_BUF;
        for (int i = dtid; i < 256 * 16; i += 256) {
            int row = i >> 4, p2 = i & 15;
            float2 v = *(const float2*)(fp + (size_t)row * HW + p2 * 2);
            *(__nv_bfloat162*)(a0 + row * A_STRIDE + p2 * 4) =
                __floats2bfloat162_rn(v.x, v.y);
        }
        const int* lp = labels + (size_t)n0 * 256;
        unsigned char* lm0 = (unsigned char*)(smem + OFF_LAB + (dom * 2) * 1024);
        for (int s = dtid; s < 1024; s += 256) {
            int px = s >> 5, sub = s & 31;
            const int4* l4 = (const int4*)(lp + px * 256 + sub * 8);
            lm0[px * 32 + sub] = (unsigned char)mask8(l4[0], l4[1]);
        }
    }
    __syncthreads();   // B + both domains' first tiles visible

    // ldsm lane decomposition
    const int r8   = lane & 7;
    const int sel8 = (lane >> 3) & 1;
    const int selk = (lane >> 4) & 1;
    const uint32_t b_base = sb + OFF_B
        + (uint32_t)(wn * 32 + sel8 * 8 + r8) * B_STRIDE + (uint32_t)selk * 16;
    const uint32_t b_base2 = b_base + 16 * B_STRIDE;
    const uint32_t a_lane_off =
        (uint32_t)(selk * 8 + r8) * A_STRIDE + (uint32_t)sel8 * 16;

    float lsum = 0.0f;   // warp0-of-domain running loss (lane = pixel row)
    int   lcnt = 0;

    int p = 0;  // buffer parity (per domain)
#pragma unroll 1
    for (int cur = gd; cur < NTILES; cur += NDOM_G, p ^= 1) {
        const int nxt = cur + NDOM_G;
        const bool pf = nxt < NTILES;
        const uint32_t a_base = sb + OFF_A + (uint32_t)(dom * 2 + p) * A_BUF + a_lane_off;
        char* anxt = smem + OFF_A + (dom * 2 + (p ^ 1)) * A_BUF;
        unsigned char* lmnxt = (unsigned char*)(smem + OFF_LAB + (dom * 2 + (p ^ 1)) * 1024);
        const float* fnx = nullptr; const int* lnx = nullptr;
        if (pf) {
            const int nn0 = nxt * TILE_P;
            fnx = feats + (size_t)(nn0 / HW) * CD * HW + (nn0 % HW);
            lnx = labels + (size_t)nn0 * 256;
        }

        float acc[2][4][4];
#pragma unroll
        for (int mb = 0; mb < 2; mb++)
#pragma unroll
            for (int nb = 0; nb < 4; nb++)
#pragma unroll
                for (int e = 0; e < 4; e++) acc[mb][nb][e] = 0.0f;

#pragma unroll
        for (int g = 0; g < 4; g++) {
            // prefetch tile nxt: A rows [g*64, g*64+64), label slots [g*256, +256)
            float4 pa0, pa1; int4 pl0, pl1;
            const int rowp = g * 64 + (dtid >> 2);
            const int q4 = dtid & 3;
            const int slot = g * 256 + dtid, pxl = slot >> 5, sub = slot & 31;
            if (pf) {
                const float4* asrc = (const float4*)(fnx + (size_t)rowp * HW);
                pa0 = asrc[q4]; pa1 = asrc[q4 + 4];
                const int4* lsrc = (const int4*)(lnx + pxl * 256 + sub * 8);
                pl0 = lsrc[0]; pl1 = lsrc[1];
            }
            // 4 ksteps of mma on tile cur (k-group g)
#pragma unroll
            for (int kk = 0; kk < 4; kk++) {
                const int ks = g * 4 + kk;
                uint32_t a[2][4], bq[2][4];
                ldsm_x4_t(a[0], a_base + (uint32_t)ks * 16 * A_STRIDE);
                ldsm_x4_t(a[1], a_base + (uint32_t)ks * 16 * A_STRIDE + 32);
                ldsm_x4(bq[0], b_base + (uint32_t)ks * 32);
                ldsm_x4(bq[1], b_base2 + (uint32_t)ks * 32);
#pragma unroll
                for (int mb = 0; mb < 2; mb++)
#pragma unroll
                    for (int nbp = 0; nbp < 2; nbp++) {
                        mma_bf16(acc[mb][2 * nbp],     a[mb], bq[nbp][0], bq[nbp][2]);
                        mma_bf16(acc[mb][2 * nbp + 1], a[mb], bq[nbp][1], bq[nbp][3]);
                    }
            }
            // drain prefetch into nxt buffers
            if (pf) {
                __nv_bfloat162 lo0 = __floats2bfloat162_rn(pa0.x, pa0.y);
                __nv_bfloat162 hi0 = __floats2bfloat162_rn(pa0.z, pa0.w);
                uint2 v0 = { *(uint32_t*)&lo0, *(uint32_t*)&hi0 };
                *(uint2*)(anxt + rowp * A_STRIDE + q4 * 8) = v0;
                __nv_bfloat162 lo1 = __floats2bfloat162_rn(pa1.x, pa1.y);
                __nv_bfloat162 hi1 = __floats2bfloat162_rn(pa1.z, pa1.w);
                uint2 v1 = { *(uint32_t*)&lo1, *(uint32_t*)&hi1 };
                *(uint2*)(anxt + rowp * A_STRIDE + (q4 + 4) * 8) = v1;
                lmnxt[pxl * 32 + sub] = (unsigned char)mask8(pl0, pl1);
            }
        }

        // ---- epilogue tile cur: s = en+ep, ep; stage to smem (parity p) ----
        const unsigned* labm = (const unsigned*)(smem + OFF_LAB + (dom * 2 + p) * 1024);
        float2* s_red = (float2*)(smem + OFF_RED + (dom * 2 + p) * 2048);
#pragma unroll
        for (int mb = 0; mb < 2; mb++) {
#pragma unroll
            for (int half = 0; half < 2; half++) {
                const int row = mb * 16 + (lane >> 2) + half * 8;   // 0..31
                const unsigned mw = labm[row * 8 + wn];
                float s = 0.0f, ep = 0.0f;
#pragma unroll
                for (int nb = 0; nb < 4; nb++) {
                    const int sh = nb * 8 + (lane & 3) * 2;
                    const unsigned bit0 = (mw >> sh) & 1u;
                    const unsigned bit1 = (mw >> (sh + 1)) & 1u;
                    float l0 = acc[mb][nb][half * 2];
                    float l1 = acc[mb][nb][half * 2 + 1];
                    float e0 = ex2(__uint_as_float(__float_as_uint(l0) ^ (bit0 << 31)));
                    float e1 = ex2(__uint_as_float(__float_as_uint(l1) ^ (bit1 << 31)));
                    s += e0;
                    s += e1;
                    ep = fmaf(e0, __uint_as_float(bit0 * 0x3F800000u), ep);
                    ep = fmaf(e1, __uint_as_float(bit1 * 0x3F800000u), ep);
                }
                s  += __shfl_xor_sync(0xffffffffu, s, 1);
                s  += __shfl_xor_sync(0xffffffffu, s, 2);
                ep += __shfl_xor_sync(0xffffffffu, ep, 1);
                ep += __shfl_xor_sync(0xffffffffu, ep, 2);
                if ((lane & 3) == 0) {
                    float2 v = { s, ep };
                    s_red[row * 8 + wn] = v;
                }
            }
        }
        // domain-private barrier: buffers flip; s_red(p) now complete
        asm volatile("bar.sync %0, 256;" :: "r"(dom + 1) : "memory");

        // warp 0 of domain: fold wn partials, accumulate loss (deterministic
        // tile order). s_red(p) is next overwritten in epilogue(t+2), which is
        // after bar(t+1); this warp reaches bar(t+1) only after these reads.
        if (dtid < 32) {
            float s = 0.0f, ep = 0.0f;
#pragma unroll
            for (int w = 0; w < 8; w++) {
                float2 v = s_red[lane * 8 + w];
                s += v.x;  ep += v.y;
            }
            float en = s - ep;
            float loss = __logf(en * ep + 1.0f);
            lsum += loss;
            lcnt += (loss != 0.0f) ? 1 : 0;
        }
    }

    // per-domain reduction (warp 0 of domain), deterministic lane order
    if (dtid < 32) {
#pragma unroll
        for (int off = 16; off > 0; off >>= 1) {
            lsum += __shfl_xor_sync(0xffffffffu, lsum, off);
            lcnt += __shfl_xor_sync(0xffffffffu, lcnt, off);
        }
        if (lane == 0) {
            g_partial[gd] = lsum;
            g_pcnt[gd]    = lcnt;
        }
    }
}

// ===================== finalize: 296 entries -> scalar =====================
__global__ void __launch_bounds__(512) pcl_fin(float* __restrict__ out)
{
    __shared__ float ss[16];
    __shared__ int   sc[16];
    const int i = threadIdx.x;
    float s = 0.0f; int c = 0;
    if (i < NDOM_G) { s = g_partial[i]; c = g_pcnt[i]; }
#pragma unroll
    for (int off = 16; off > 0; off >>= 1) {
        s += __shfl_xor_sync(0xffffffffu, s, off);
        c += __shfl_xor_sync(0xffffffffu, c, off);
    }
    const int lane = i & 31, wid = i >> 5;
    if (lane == 0) { ss[wid] = s; sc[wid] = c; }
    __syncthreads();
    if (i == 0) {
        float t = 0.0f; int c2 = 0;
#pragma unroll
        for (int w = 0; w < 16; w++) { t += ss[w]; c2 += sc[w]; }
        out[0] = (c2 == 0) ? 0.0f : t / (float)(c2 < 1 ? 1 : c2);
    }
}

extern "C" void kernel_launch(void* const* d_in, const int* in_sizes, int n_in,
                              void* d_out, int out_size)
{
    const float* feats  = (const float*)d_in[0];
    const float* queue  = (const float*)d_in[1];
    const int*   labels = (const int*)d_in[2];
    float* out = (float*)d_out;

    static bool attr_set = false;
    if (!attr_set) {
        cudaFuncSetAttribute(pcl_main,
                             cudaFuncAttributeMaxDynamicSharedMemorySize, SMEM_SZ);
        attr_set = true;
    }

    pcl_main<<<GRID, NTHR, SMEM_SZ>>>(feats, queue, labels);
    pcl_fin<<<1, 512>>>(out);
}

// round 16
// speedup vs baseline: 1.1142x; 1.0876x over previous
#include <cuda_runtime.h>
#include <cuda_bf16.h>
#include <cstdint>

#define NPIX   262144
#define CD     256
#define HW     16384
#define TILE_P 32
#define NTILES (NPIX / TILE_P)      // 8192 tiles of 32 px
#define GRID   148
#define NTHR   512                  // 2 domains x 256
#define NDOM_G (GRID * 2)           // 296 global domains
// total logit scale: (1/T)*log2(e) = 20.60993; split: feats x8, queue x QB
#define FSCALE 8.0f
#define QB     2.5762411444445775f  // 20.60993 / 8

// smem layout (bytes). fp8: B rows 256B, A rows (px-major) 256B; pad to 272
// (68 words; row-start bank = 4*row mod 32 -> conflict-free ldsm/STS phases)
#define B_STRIDE 272
#define A_STRIDE 272
#define A_BUF    (32 * A_STRIDE)      // 8704 per buffer (32 px rows)
#define OFF_B    0                    // 256*272 = 69632
#define OFF_A    69632                // 4 buffers (dom,parity) -> +34816
#define OFF_LAB  (OFF_A + 4 * A_BUF)  // 104448 : 4 x 1024 (32 px * 32 bytes)
#define OFF_RED  (OFF_LAB + 4 * 1024) // 108544 : 4 x 2048 (32 rows x 8 wn x float2)
#define SMEM_SZ  (OFF_RED + 4 * 2048) // 116736

__device__ float g_partial[NDOM_G];
__device__ int   g_pcnt[NDOM_G];

__device__ __forceinline__ uint32_t smem_u32(const void* p) {
    uint32_t a;
    asm("{ .reg .u64 t; cvta.to.shared.u64 t, %1; cvt.u32.u64 %0, t; }" : "=r"(a) : "l"(p));
    return a;
}
__device__ __forceinline__ void ldsm_x4(uint32_t* r, uint32_t addr) {
    asm volatile("ldmatrix.sync.aligned.m8n8.x4.shared.b16 {%0,%1,%2,%3}, [%4];"
                 : "=r"(r[0]), "=r"(r[1]), "=r"(r[2]), "=r"(r[3]) : "r"(addr));
}
// fp8 e4m3 mma, K=32: A/B fragments are the b16 k16 fragments reinterpreted
__device__ __forceinline__ void mma_fp8(float* d, const uint32_t* a,
                                        uint32_t b0, uint32_t b1) {
    asm volatile(
        "mma.sync.aligned.m16n8k32.row.col.f32.e4m3.e4m3.f32 "
        "{%0,%1,%2,%3}, {%4,%5,%6,%7}, {%8,%9}, {%0,%1,%2,%3};"
        : "+f"(d[0]), "+f"(d[1]), "+f"(d[2]), "+f"(d[3])
        : "r"(a[0]), "r"(a[1]), "r"(a[2]), "r"(a[3]), "r"(b0), "r"(b1));
}
__device__ __forceinline__ float ex2(float x) {
    float r;
    asm("ex2.approx.f32 %0, %1;" : "=f"(r) : "f"(x));
    return r;
}
// pack 4 floats -> 4 e4m3 bytes (byte i = f_i)
__device__ __forceinline__ uint32_t pack_e4m3_4(float f0, float f1, float f2, float f3) {
    unsigned short h01, h23;
    asm("cvt.rn.satfinite.e4m3x2.f32 %0, %1, %2;" : "=h"(h01) : "f"(f1), "f"(f0));
    asm("cvt.rn.satfinite.e4m3x2.f32 %0, %1, %2;" : "=h"(h23) : "f"(f3), "f"(f2));
    uint32_t r;
    asm("mov.b32 %0, {%1, %2};" : "=r"(r) : "h"(h01), "h"(h23));
    return r;
}
// labels are {0,1} int32: arithmetic pack
__device__ __forceinline__ unsigned mask8(const int4& v0, const int4& v1) {
    unsigned m;
    m  = ((unsigned)v0.x & 1u);
    m += ((unsigned)v0.y & 1u) << 1;
    m += ((unsigned)v0.z & 1u) << 2;
    m += ((unsigned)v0.w & 1u) << 3;
    m += ((unsigned)v1.x & 1u) << 4;
    m += ((unsigned)v1.y & 1u) << 5;
    m += ((unsigned)v1.z & 1u) << 6;
    m += ((unsigned)v1.w & 1u) << 7;
    return m;
}

// ===================== persistent fused main kernel =====================
// 148 CTAs x 512 thr = 2 independent domains of 256 thr (8 warps, warp tile
// 32x32). FP8 e4m3 GEMM: A px-major [m][k], B class-major [n][k]; both
// operands load with plain b16 ldsm.x4; 8 ksteps of m16n8k32.
__global__ void __launch_bounds__(NTHR, 1)
pcl_main(const float* __restrict__ feats, const float* __restrict__ queue,
         const int* __restrict__ labels)
{
    extern __shared__ char smem[];
    const uint32_t sb = smem_u32(smem);
    const int tid = threadIdx.x, lane = tid & 31;
    const int dom = tid >> 8;            // 0..1
    const int dtid = tid & 255;          // thread within domain
    const int wn = dtid >> 5;            // 0..7 : warp within domain
    const int gd = blockIdx.x * 2 + dom; // global domain id 0..295

    // ---- stage B once (whole block): queue fp32 -> e4m3 x QB ----
    for (int i = tid; i < 256 * 64; i += NTHR) {
        int n = i >> 6, k4 = i & 63;
        float4 v = *(const float4*)(queue + n * 256 + k4 * 4);
        *(uint32_t*)(smem + OFF_B + n * B_STRIDE + k4 * 4) =
            pack_e4m3_4(v.x * QB, v.y * QB, v.z * QB, v.w * QB);
    }
    // ---- stage first tile (per domain, buffer parity 0) ----
    {
        const int n0 = gd * TILE_P;
        const float* fp = feats + (size_t)(n0 / HW) * CD * HW + (n0 % HW);
        char* a0 = smem + OFF_A + (dom * 2) * A_BUF;
#pragma unroll
        for (int g = 0; g < 4; g++) {
            const int c0 = g * 64 + wn * 8;
            float f[8];
#pragma unroll
            for (int j = 0; j < 8; j++)
                f[j] = fp[(size_t)(c0 + j) * HW + lane] * FSCALE;
            uint2 v = { pack_e4m3_4(f[0], f[1], f[2], f[3]),
                        pack_e4m3_4(f[4], f[5], f[6], f[7]) };
            *(uint2*)(a0 + lane * A_STRIDE + c0) = v;
        }
        const int* lp = labels + (size_t)n0 * 256;
        unsigned char* lm0 = (unsigned char*)(smem + OFF_LAB + (dom * 2) * 1024);
        for (int s = dtid; s < 1024; s += 256) {
            int px = s >> 5, sub = s & 31;
            const int4* l4 = (const int4*)(lp + px * 256 + sub * 8);
            lm0[px * 32 + sub] = (unsigned char)mask8(l4[0], l4[1]);
        }
    }
    __syncthreads();   // B + both domains' first tiles visible

    // ldsm lane decomposition (both operands: plain b16 x4 pattern)
    const uint32_t a_lane_off = (uint32_t)(lane & 15) * A_STRIDE
                              + (uint32_t)(lane >> 4) * 16;
    const uint32_t b_base = sb + OFF_B
        + (uint32_t)(wn * 32 + (lane & 15)) * B_STRIDE + (uint32_t)(lane >> 4) * 16;
    const uint32_t b_base2 = b_base + 16 * B_STRIDE;

    float lsum = 0.0f;   // warp0-of-domain running loss
    int   lcnt = 0;

    int p = 0;  // buffer parity (per domain)
#pragma unroll 1
    for (int cur = gd; cur < NTILES; cur += NDOM_G, p ^= 1) {
        const int nxt = cur + NDOM_G;
        const bool pf = nxt < NTILES;
        const uint32_t a_base = sb + OFF_A + (uint32_t)(dom * 2 + p) * A_BUF + a_lane_off;
        char* anxt = smem + OFF_A + (dom * 2 + (p ^ 1)) * A_BUF;
        unsigned char* lmnxt = (unsigned char*)(smem + OFF_LAB + (dom * 2 + (p ^ 1)) * 1024);
        const float* fnx = nullptr; const int* lnx = nullptr;
        if (pf) {
            const int nn0 = nxt * TILE_P;
            fnx = feats + (size_t)(nn0 / HW) * CD * HW + (nn0 % HW);
            lnx = labels + (size_t)nn0 * 256;
        }

        float acc[2][4][4];
#pragma unroll
        for (int mb = 0; mb < 2; mb++)
#pragma unroll
            for (int nb = 0; nb < 4; nb++)
#pragma unroll
                for (int e = 0; e < 4; e++) acc[mb][nb][e] = 0.0f;

#pragma unroll
        for (int g = 0; g < 4; g++) {
            // prefetch tile nxt: 8 channel rows (this warp), labels
            float pf8[8]; int4 pl0, pl1;
            const int c0 = g * 64 + wn * 8;
            const int slot = g * 256 + dtid, pxl = slot >> 5, sub = slot & 31;
            if (pf) {
#pragma unroll
                for (int j = 0; j < 8; j++)
                    pf8[j] = fnx[(size_t)(c0 + j) * HW + lane];
                const int4* lsrc = (const int4*)(lnx + pxl * 256 + sub * 8);
                pl0 = lsrc[0]; pl1 = lsrc[1];
            }
            // 2 ksteps of fp8 mma on tile cur (k-group g = 64 channels)
#pragma unroll
            for (int kk = 0; kk < 2; kk++) {
                const int ks = g * 2 + kk;
                uint32_t a[2][4], bq[2][4];
                ldsm_x4(a[0], a_base + (uint32_t)ks * 32);
                ldsm_x4(a[1], a_base + 16 * A_STRIDE + (uint32_t)ks * 32);
                ldsm_x4(bq[0], b_base + (uint32_t)ks * 32);
                ldsm_x4(bq[1], b_base2 + (uint32_t)ks * 32);
#pragma unroll
                for (int mb = 0; mb < 2; mb++) {
                    mma_fp8(acc[mb][0], a[mb], bq[0][0], bq[0][2]);
                    mma_fp8(acc[mb][1], a[mb], bq[0][1], bq[0][3]);
                    mma_fp8(acc[mb][2], a[mb], bq[1][0], bq[1][2]);
                    mma_fp8(acc[mb][3], a[mb], bq[1][1], bq[1][3]);
                }
            }
            // drain prefetch into nxt buffers (px-major fp8)
            if (pf) {
                uint2 v = { pack_e4m3_4(pf8[0] * FSCALE, pf8[1] * FSCALE,
                                        pf8[2] * FSCALE, pf8[3] * FSCALE),
                            pack_e4m3_4(pf8[4] * FSCALE, pf8[5] * FSCALE,
                                        pf8[6] * FSCALE, pf8[7] * FSCALE) };
                *(uint2*)(anxt + lane * A_STRIDE + c0) = v;
                lmnxt[pxl * 32 + sub] = (unsigned char)mask8(pl0, pl1);
            }
        }

        // ---- epilogue tile cur: s = en+ep, ep; stage to smem (parity p) ----
        const unsigned* labm = (const unsigned*)(smem + OFF_LAB + (dom * 2 + p) * 1024);
        float2* s_red = (float2*)(smem + OFF_RED + (dom * 2 + p) * 2048);
#pragma unroll
        for (int mb = 0; mb < 2; mb++) {
#pragma unroll
            for (int half = 0; half < 2; half++) {
                const int row = mb * 16 + (lane >> 2) + half * 8;   // 0..31
                const unsigned mw = labm[row * 8 + wn];
                float s = 0.0f, ep = 0.0f;
#pragma unroll
                for (int nb = 0; nb < 4; nb++) {
                    const int sh = nb * 8 + (lane & 3) * 2;
                    const unsigned bit0 = (mw >> sh) & 1u;
                    const unsigned bit1 = (mw >> (sh + 1)) & 1u;
                    float l0 = acc[mb][nb][half * 2];
                    float l1 = acc[mb][nb][half * 2 + 1];
                    float e0 = ex2(__uint_as_float(__float_as_uint(l0) ^ (bit0 << 31)));
                    float e1 = ex2(__uint_as_float(__float_as_uint(l1) ^ (bit1 << 31)));
                    s += e0;
                    s += e1;
                    ep = fmaf(e0, __uint_as_float(bit0 * 0x3F800000u), ep);
                    ep = fmaf(e1, __uint_as_float(bit1 * 0x3F800000u), ep);
                }
                s  += __shfl_xor_sync(0xffffffffu, s, 1);
                s  += __shfl_xor_sync(0xffffffffu, s, 2);
                ep += __shfl_xor_sync(0xffffffffu, ep, 1);
                ep += __shfl_xor_sync(0xffffffffu, ep, 2);
                if ((lane & 3) == 0) {
                    float2 v = { s, ep };
                    s_red[row * 8 + wn] = v;
                }
            }
        }
        // domain-private barrier: buffers flip; s_red(p) complete
        asm volatile("bar.sync %0, 256;" :: "r"(dom + 1) : "memory");

        // warp 0 of domain: fold wn partials, accumulate loss (deterministic)
        if (dtid < 32) {
            float s = 0.0f, ep = 0.0f;
#pragma unroll
            for (int w = 0; w < 8; w++) {
                float2 v = s_red[lane * 8 + w];
                s += v.x;  ep += v.y;
            }
            float en = s - ep;
            float loss = __logf(en * ep + 1.0f);
            lsum += loss;
            lcnt += (loss != 0.0f) ? 1 : 0;
        }
    }

    // per-domain reduction (warp 0 of domain)
    if (dtid < 32) {
#pragma unroll
        for (int off = 16; off > 0; off >>= 1) {
            lsum += __shfl_xor_sync(0xffffffffu, lsum, off);
            lcnt += __shfl_xor_sync(0xffffffffu, lcnt, off);
        }
        if (lane == 0) {
            g_partial[gd] = lsum;
            g_pcnt[gd]    = lcnt;
        }
    }
}

// ===================== finalize: 296 entries -> scalar =====================
__global__ void __launch_bounds__(512) pcl_fin(float* __restrict__ out)
{
    __shared__ float ss[16];
    __shared__ int   sc[16];
    const int i = threadIdx.x;
    float s = 0.0f; int c = 0;
    if (i < NDOM_G) { s = g_partial[i]; c = g_pcnt[i]; }
#pragma unroll
    for (int off = 16; off > 0; off >>= 1) {
        s += __shfl_xor_sync(0xffffffffu, s, off);
        c += __shfl_xor_sync(0xffffffffu, c, off);
    }
    const int lane = i & 31, wid = i >> 5;
    if (lane == 0) { ss[wid] = s; sc[wid] = c; }
    __syncthreads();
    if (i == 0) {
        float t = 0.0f; int c2 = 0;
#pragma unroll
        for (int w = 0; w < 16; w++) { t += ss[w]; c2 += sc[w]; }
        out[0] = (c2 == 0) ? 0.0f : t / (float)(c2 < 1 ? 1 : c2);
    }
}

extern "C" void kernel_launch(void* const* d_in, const int* in_sizes, int n_in,
                              void* d_out, int out_size)
{
    const float* feats  = (const float*)d_in[0];
    const float* queue  = (const float*)d_in[1];
    const int*   labels = (const int*)d_in[2];
    float* out = (float*)d_out;

    static bool attr_set = false;
    if (!attr_set) {
        cudaFuncSetAttribute(pcl_main,
                             cudaFuncAttributeMaxDynamicSharedMemorySize, SMEM_SZ);
        attr_set = true;
    }

    pcl_main<<<GRID, NTHR, SMEM_SZ>>>(feats, queue, labels);
    pcl_fin<<<1, 512>>>(out);
}